// round 17
// baseline (speedup 1.0000x reference)
#include <cuda_runtime.h>
#include <cstdint>

#define N_NODES 4096
#define F_IN    512
#define HD1     64
#define NH1     8
#define C2      16
#define MAXDEG  256

#define SA 36     // A smem row stride: fragment bank = 4g+t, conflict-free
#define SB 72     // B smem row stride: fragment bank = 8t+g, conflict-free
#define STAGES 3

__device__ int   g_nbr[N_NODES * MAXDEG];
__device__ int   g_deg[N_NODES];
__device__ float g_h1 [N_NODES * HD1];
__device__ float g_es1[N_NODES * NH1];
__device__ float g_ed1[N_NODES * NH1];
__device__ float g_h2 [N_NODES * C2];
__device__ float g_es2[N_NODES];
__device__ float g_ed2[N_NODES];

// ---------------------------------------------------------------------------
// helpers
// ---------------------------------------------------------------------------
__device__ __forceinline__ uint32_t f2tf32(float x)
{
    uint32_t r;
    asm("cvt.rna.tf32.f32 %0, %1;" : "=r"(r) : "f"(x));
    return r;
}
__device__ __forceinline__ void cvt_split(float x, uint32_t& hi, uint32_t& lo)
{
    hi = f2tf32(x);
    lo = f2tf32(x - __uint_as_float(hi));
}

#define MMA_TF32(c, A0, A1, A2, A3, B0, B1)                                   \
    asm volatile(                                                             \
        "mma.sync.aligned.m16n8k8.row.col.f32.tf32.tf32.f32 "                 \
        "{%0,%1,%2,%3}, {%4,%5,%6,%7}, {%8,%9}, {%0,%1,%2,%3};"               \
        : "+f"(c[0]), "+f"(c[1]), "+f"(c[2]), "+f"(c[3])                      \
        : "r"(A0), "r"(A1), "r"(A2), "r"(A3), "r"(B0), "r"(B1))

#define CP_ASYNC16(dst_u32, src_ptr)                                          \
    asm volatile("cp.async.cg.shared.global [%0], [%1], 16;"                  \
                 :: "r"(dst_u32), "l"(src_ptr))
#define CP_COMMIT() asm volatile("cp.async.commit_group;")
#define CP_WAIT1()  asm volatile("cp.async.wait_group 1;")

// ---------------------------------------------------------------------------
// K1: GEMM1 h1 = x @ W1 via tf32 tensor cores (3xTF32 split precision).
// 3-stage cp.async pipeline of RAW fp32 tiles; cvt_split at fragment load.
// grid=128, 256 thr (8 warps = 2x4 warp-tiles of 16x16). Fused es1/ed1.
// ---------------------------------------------------------------------------
__global__ __launch_bounds__(256) void k_gemm1(const float* __restrict__ X,
                                               const float* __restrict__ W,
                                               const float* __restrict__ a_src,
                                               const float* __restrict__ a_dst)
{
    __shared__ float sA[STAGES][32 * SA];   // raw fp32 A [m][k]
    __shared__ float sB[STAGES][32 * SB];   // raw fp32 B [k][n]

    const int tid  = threadIdx.x;
    const int lane = tid & 31;
    const int wrp  = tid >> 5;
    const int wm   = wrp >> 2;           // 0..1
    const int wn   = wrp & 3;            // 0..3
    const int m0   = blockIdx.x * 32;

    const int g = lane >> 2;             // 0..7
    const int t = lane & 3;              // 0..3

    // loader coords
    const int ar  = tid >> 3;            // A row 0..31
    const int ac4 = tid & 7;             // A k-chunk
    const int br  = tid >> 4;            // B row 0..15 (+16)
    const int bc4 = tid & 15;            // B n-chunk

    float acc[2][4] = {};

    // smem byte addresses (per-stage base computed in loop)
    const uint32_t sA_base = (uint32_t)__cvta_generic_to_shared(&sA[0][0]);
    const uint32_t sB_base = (uint32_t)__cvta_generic_to_shared(&sB[0][0]);
    const uint32_t sA_stage = 32 * SA * 4;
    const uint32_t sB_stage = 32 * SB * 4;
    const uint32_t dA_off = (uint32_t)(ar * SA + ac4 * 4) * 4;
    const uint32_t dB0_off = (uint32_t)(br * SB + bc4 * 4) * 4;
    const uint32_t dB1_off = (uint32_t)((br + 16) * SB + bc4 * 4) * 4;

    // prefetch tiles 0,1
    #pragma unroll
    for (int p = 0; p < STAGES - 1; p++) {
        const int kt = p * 32;
        CP_ASYNC16(sA_base + p * sA_stage + dA_off,
                   X + (size_t)(m0 + ar) * F_IN + kt + ac4 * 4);
        CP_ASYNC16(sB_base + p * sB_stage + dB0_off,
                   W + (size_t)(kt + br) * HD1 + bc4 * 4);
        CP_ASYNC16(sB_base + p * sB_stage + dB1_off,
                   W + (size_t)(kt + br + 16) * HD1 + bc4 * 4);
        CP_COMMIT();
    }

    const int rowA = wm * 16 + g;
    const int colB = wn * 16 + g;

    #pragma unroll 1
    for (int tt = 0; tt < 16; tt++) {
        CP_WAIT1();            // tile tt landed (tile tt+1 may be pending)
        __syncthreads();       // all compute of tt-1 done; stage reuse safe

        // issue loads for tile tt+2 into stage (tt+2)%STAGES
        if (tt + 2 < 16) {
            const int s  = (tt + 2) % STAGES;
            const int kt = (tt + 2) * 32;
            CP_ASYNC16(sA_base + s * sA_stage + dA_off,
                       X + (size_t)(m0 + ar) * F_IN + kt + ac4 * 4);
            CP_ASYNC16(sB_base + s * sB_stage + dB0_off,
                       W + (size_t)(kt + br) * HD1 + bc4 * 4);
            CP_ASYNC16(sB_base + s * sB_stage + dB1_off,
                       W + (size_t)(kt + br + 16) * HD1 + bc4 * 4);
        }
        CP_COMMIT();           // keep group count uniform (empty ok)

        // compute on stage tt%STAGES
        const float* A = sA[tt % STAGES];
        const float* B = sB[tt % STAGES];
        #pragma unroll
        for (int kk = 0; kk < 32; kk += 8) {
            const int ka = kk + t;
            float a0r = A[ rowA      * SA + ka    ];
            float a1r = A[(rowA + 8) * SA + ka    ];
            float a2r = A[ rowA      * SA + ka + 4];
            float a3r = A[(rowA + 8) * SA + ka + 4];
            float b00r = B[(ka    ) * SB + colB    ];
            float b01r = B[(ka + 4) * SB + colB    ];
            float b10r = B[(ka    ) * SB + colB + 8];
            float b11r = B[(ka + 4) * SB + colB + 8];

            uint32_t ah0,al0,ah1,al1,ah2,al2,ah3,al3;
            cvt_split(a0r, ah0, al0); cvt_split(a1r, ah1, al1);
            cvt_split(a2r, ah2, al2); cvt_split(a3r, ah3, al3);
            uint32_t bh00,bl00,bh01,bl01,bh10,bl10,bh11,bl11;
            cvt_split(b00r, bh00, bl00); cvt_split(b01r, bh01, bl01);
            cvt_split(b10r, bh10, bl10); cvt_split(b11r, bh11, bl11);

            MMA_TF32(acc[0], ah0, ah1, ah2, ah3, bh00, bh01);
            MMA_TF32(acc[1], ah0, ah1, ah2, ah3, bh10, bh11);
            MMA_TF32(acc[0], al0, al1, al2, al3, bh00, bh01);
            MMA_TF32(acc[1], al0, al1, al2, al3, bh10, bh11);
            MMA_TF32(acc[0], ah0, ah1, ah2, ah3, bl00, bl01);
            MMA_TF32(acc[1], ah0, ah1, ah2, ah3, bl10, bl11);
        }
        __syncthreads();
    }

    // ---- epilogue: write h1 + fused es1/ed1 (round-16 layout, unchanged) ----
    const int r0 = m0 + wm * 16 + g;
    const int r1 = r0 + 8;
    #pragma unroll
    for (int tl = 0; tl < 2; tl++) {
        const int c0 = wn * 16 + tl * 8 + 2 * t;
        *(float2*)(g_h1 + (size_t)r0 * HD1 + c0) = make_float2(acc[tl][0], acc[tl][1]);
        *(float2*)(g_h1 + (size_t)r1 * HD1 + c0) = make_float2(acc[tl][2], acc[tl][3]);
    }

    #pragma unroll
    for (int tl = 0; tl < 2; tl++) {
        const int c0 = wn * 16 + tl * 8 + 2 * t;
        const int h  = 2 * wn + tl;
        const float as0 = __ldg(&a_src[c0]),  as1 = __ldg(&a_src[c0 + 1]);
        const float ad0 = __ldg(&a_dst[c0]),  ad1 = __ldg(&a_dst[c0 + 1]);
        float sr0 = acc[tl][0] * as0 + acc[tl][1] * as1;
        float sr1 = acc[tl][2] * as0 + acc[tl][3] * as1;
        float dr0 = acc[tl][0] * ad0 + acc[tl][1] * ad1;
        float dr1 = acc[tl][2] * ad0 + acc[tl][3] * ad1;
        sr0 += __shfl_xor_sync(0xFFFFFFFFu, sr0, 1);
        sr0 += __shfl_xor_sync(0xFFFFFFFFu, sr0, 2);
        sr1 += __shfl_xor_sync(0xFFFFFFFFu, sr1, 1);
        sr1 += __shfl_xor_sync(0xFFFFFFFFu, sr1, 2);
        dr0 += __shfl_xor_sync(0xFFFFFFFFu, dr0, 1);
        dr0 += __shfl_xor_sync(0xFFFFFFFFu, dr0, 2);
        dr1 += __shfl_xor_sync(0xFFFFFFFFu, dr1, 1);
        dr1 += __shfl_xor_sync(0xFFFFFFFFu, dr1, 2);
        if (t == 0) {
            g_es1[r0 * NH1 + h] = sr0;
            g_es1[r1 * NH1 + h] = sr1;
            g_ed1[r0 * NH1 + h] = dr0;
            g_ed1[r1 * NH1 + h] = dr1;
        }
    }
}

// ---------------------------------------------------------------------------
// K2: FUSED adjacency-scan + layer-1 attention + ELU + layer-2 row + scores.
// (round-13, unchanged)
// ---------------------------------------------------------------------------
__global__ __launch_bounds__(64) void k_attn1(const void* __restrict__ adj,
                                              const float* __restrict__ W2,
                                              const float* __restrict__ a2_src,
                                              const float* __restrict__ a2_dst)
{
    const int i    = blockIdx.x;
    const int tid  = threadIdx.x;
    const int lane = tid & 31;
    const int wid  = tid >> 5;
    const uint8_t* u8 = (const uint8_t*)adj;

    __shared__ int   snbr[MAXDEG];
    __shared__ float ew[MAXDEG * NH1];
    __shared__ float red[2][NH1];
    __shared__ float ssv[NH1];
    __shared__ float sa1[HD1];
    __shared__ int   wsum[2];

    int fmt;
    if (u8[(size_t)N_NODES + 1] == 1)            fmt = 0;
    else if (u8[4 * ((size_t)N_NODES + 1)] == 1) fmt = 1;
    else                                         fmt = 2;

    uint64_t mask = 0;
    #pragma unroll
    for (int r = 0; r < 16; r++) {
        const int cbase = (r * 64 + tid) * 4;
        uint64_t p0, p1, p2, p3;
        if (fmt == 2) {
            float4 v = *(const float4*)((const float*)adj + (size_t)i * N_NODES + cbase);
            p0 = v.x != 0.f; p1 = v.y != 0.f; p2 = v.z != 0.f; p3 = v.w != 0.f;
        } else if (fmt == 1) {
            int4 v = *(const int4*)((const int*)adj + (size_t)i * N_NODES + cbase);
            p0 = v.x != 0; p1 = v.y != 0; p2 = v.z != 0; p3 = v.w != 0;
        } else {
            uint32_t w = *(const uint32_t*)(u8 + (size_t)i * N_NODES + cbase);
            p0 = (w & 0x000000FFu) != 0;
            p1 = (w & 0x0000FF00u) != 0;
            p2 = (w & 0x00FF0000u) != 0;
            p3 = (w & 0xFF000000u) != 0;
        }
        mask |= (p0 << (r * 4)) | (p1 << (r * 4 + 1)) |
                (p2 << (r * 4 + 2)) | (p3 << (r * 4 + 3));
    }
    const int cnt = (int)__popcll(mask);

    int incl = cnt;
    #pragma unroll
    for (int o = 1; o < 32; o <<= 1) {
        int t = __shfl_up_sync(0xFFFFFFFFu, incl, o);
        if (lane >= o) incl += t;
    }
    if (lane == 31) wsum[wid] = incl;
    __syncthreads();
    const int total = wsum[0] + wsum[1];
    const int deg   = (total > MAXDEG) ? MAXDEG : total;
    if (tid == 0) g_deg[i] = deg;

    {
        int base = ((wid == 1) ? wsum[0] : 0) + (incl - cnt);
        int* gout = g_nbr + (size_t)i * MAXDEG;
        #pragma unroll
        for (int r = 0; r < 16; r++) {
            const int cbase = (r * 64 + tid) * 4;
            #pragma unroll
            for (int q = 0; q < 4; q++) {
                if ((mask >> (r * 4 + q)) & 1ull) {
                    if (base < MAXDEG) {
                        snbr[base] = cbase + q;
                        gout[base] = cbase + q;
                    }
                    base++;
                }
            }
        }
    }
    __syncthreads();

    const int h  = tid & 7;
    const int wh = tid >> 5;
    const int tot = deg * NH1;
    const float esi_h = g_es1[i * NH1 + h];

    float sloc = 0.f;
    for (int idx = tid; idx < tot; idx += 64) {
        int j = idx >> 3;
        float e = esi_h + g_ed1[snbr[j] * NH1 + h];
        e = (e > 0.f) ? e : 0.2f * e;
        float w = __expf(e);
        ew[idx] = w;
        sloc += w;
    }
    sloc += __shfl_xor_sync(0xFFFFFFFFu, sloc, 8);
    sloc += __shfl_xor_sync(0xFFFFFFFFu, sloc, 16);
    if ((tid & 31) < 8) red[wh][h] = sloc;
    __syncthreads();
    if (tid < NH1) ssv[tid] = 1.f / (red[0][tid] + red[1][tid]);
    __syncthreads();

    {
        const int hh = tid >> 3;
        const float inv = ssv[hh];
        float a0 = 0.f, a1 = 0.f, a2 = 0.f, a3 = 0.f;
        int j = 0;
        for (; j + 4 <= deg; j += 4) {
            a0 += ew[(j+0) * NH1 + hh] * g_h1[(size_t)snbr[j+0] * HD1 + tid];
            a1 += ew[(j+1) * NH1 + hh] * g_h1[(size_t)snbr[j+1] * HD1 + tid];
            a2 += ew[(j+2) * NH1 + hh] * g_h1[(size_t)snbr[j+2] * HD1 + tid];
            a3 += ew[(j+3) * NH1 + hh] * g_h1[(size_t)snbr[j+3] * HD1 + tid];
        }
        for (; j < deg; j++)
            a0 += ew[j * NH1 + hh] * g_h1[(size_t)snbr[j] * HD1 + tid];
        float acc = ((a0 + a1) + (a2 + a3)) * inv;
        acc = (acc > 0.f) ? acc : expm1f(acc);   // ELU
        sa1[tid] = acc;
    }
    __syncthreads();

    if (tid < C2) {
        float v = 0.f;
        #pragma unroll 8
        for (int k = 0; k < HD1; k++)
            v += sa1[k] * __ldg(&W2[k * C2 + tid]);
        g_h2[(size_t)i * C2 + tid] = v;

        float s = v * a2_src[tid];
        float d = v * a2_dst[tid];
        #pragma unroll
        for (int o = 8; o >= 1; o >>= 1) {
            s += __shfl_xor_sync(0x0000FFFFu, s, o);
            d += __shfl_xor_sync(0x0000FFFFu, d, o);
        }
        if (tid == 0) {
            g_es2[i] = s;
            g_ed2[i] = d;
        }
    }
}

// ---------------------------------------------------------------------------
// K3: layer-2 sparse attention. Single fused pass (unchanged).
// ---------------------------------------------------------------------------
__global__ __launch_bounds__(256) void k_attn2(float* __restrict__ out)
{
    const int w    = threadIdx.x >> 5;
    const int lane = threadIdx.x & 31;
    const int i    = blockIdx.x * 8 + w;
    const int deg  = g_deg[i];

    __shared__ int snbr[8][MAXDEG];

    for (int j = lane; j < deg; j += 32)
        snbr[w][j] = g_nbr[(size_t)i * MAXDEG + j];
    __syncwarp();

    const float esi = g_es2[i];
    const int g  = lane >> 2;
    const int c4 = lane & 3;

    float4 acc = make_float4(0.f, 0.f, 0.f, 0.f);
    float  wsum = 0.f;
    for (int base = 0; base < deg; base += 8) {
        int j = base + g;
        if (j < deg) {
            int   n  = snbr[w][j];
            float e  = esi + g_ed2[n];
            e = (e > 0.f) ? e : 0.2f * e;
            float wt = __expf(e);
            float4 v = *(const float4*)(g_h2 + (size_t)n * C2 + c4 * 4);
            acc.x += wt * v.x;
            acc.y += wt * v.y;
            acc.z += wt * v.z;
            acc.w += wt * v.w;
            wsum  += wt;
        }
    }
    #pragma unroll
    for (int o = 4; o <= 16; o <<= 1) {
        acc.x += __shfl_xor_sync(0xFFFFFFFFu, acc.x, o);
        acc.y += __shfl_xor_sync(0xFFFFFFFFu, acc.y, o);
        acc.z += __shfl_xor_sync(0xFFFFFFFFu, acc.z, o);
        acc.w += __shfl_xor_sync(0xFFFFFFFFu, acc.w, o);
        wsum  += __shfl_xor_sync(0xFFFFFFFFu, wsum,  o);
    }
    if (lane < 4) {
        const float inv = 1.f / wsum;
        float4 r = make_float4(acc.x * inv, acc.y * inv, acc.z * inv, acc.w * inv);
        *(float4*)(out + (size_t)i * C2 + lane * 4) = r;
    }
}

// ---------------------------------------------------------------------------
// Launch: strictly sequential on the capture stream. 3 kernels.
// ---------------------------------------------------------------------------
extern "C" void kernel_launch(void* const* d_in, const int* in_sizes, int n_in,
                              void* d_out, int out_size)
{
    const float* x      = (const float*)d_in[0];
    const void*  adj    = d_in[1];
    const float* W1     = (const float*)d_in[2];
    const float* a1_src = (const float*)d_in[3];
    const float* a1_dst = (const float*)d_in[4];
    const float* W2     = (const float*)d_in[5];
    const float* a2_src = (const float*)d_in[6];
    const float* a2_dst = (const float*)d_in[7];
    float* out = (float*)d_out;

    k_gemm1<<<N_NODES / 32, 256>>>(x, W1, a1_src, a1_dst);
    k_attn1<<<N_NODES, 64>>>(adj, W2, a2_src, a2_dst);
    k_attn2<<<N_NODES / 8, 256>>>(out);
}